// round 1
// baseline (speedup 1.0000x reference)
#include <cuda_runtime.h>
#include <cstdint>

typedef unsigned long long ULL;

// Problem constants (fixed shapes per reference)
constexpr int Bz = 16, C = 64, H = 64, W = 64;
constexpr int N  = Bz * H * W;     // 65536 rows
constexpr int K  = 1024;           // codes
constexpr int HW = H * W;          // 4096
constexpr int CHW = C * HW;        // 262144

// argmin kernel tiling
constexpr int TM = 128;            // rows per block
constexpr int TN = 128;            // codes per chunk
constexpr int KC = 16;             // k per smem stage
constexpr int PA = 258;            // As2 pitch (floats): duplicated rows, 2*TM=256 used
constexpr int PB = 132;            // Bs pitch (floats): TN=128 used

// Device scratch (no allocations allowed)
__device__ int    g_idx[N];
__device__ float  g_enorm[K];
__device__ double g_partials[256];

// ---------------------------------------------------------------------------
// Kernel 0: ||e_k||^2 per code, replicating reference rounding:
//   emb*emb elementwise (fp32 mul), then sum (fp32 adds), sequential order.
// ---------------------------------------------------------------------------
__global__ void enorm_kernel(const float* __restrict__ emb) {
    int code = blockIdx.x * blockDim.x + threadIdx.x;
    if (code < K) {
        const float* e = emb + code * C;
        float acc = 0.f;
        #pragma unroll
        for (int c = 0; c < C; c++) {
            float v = e[c];
            acc = __fadd_rn(acc, __fmul_rn(v, v));
        }
        g_enorm[code] = acc;
    }
}

// ---------------------------------------------------------------------------
// Kernel 1: fused fp32 GEMM-score + per-row argmin.
// Per block: 128 rows x all 1024 codes (8 chunks of 128).
// Per thread (16x16 grid): 8 rows x 8 codes (4 adjacent pairs, stride 32).
// Inner product via packed fma.rn.f32x2 (full-rate fp32 on Blackwell).
// Score d = (znorm - 2*S) + enorm with explicit fp32 rounding, matching
// the reference's ulp(64)-grid quantization. Ties -> lowest index.
// ---------------------------------------------------------------------------
__global__ __launch_bounds__(256, 2)
void argmin_kernel(const float* __restrict__ z, const float* __restrict__ emb) {
    __shared__ alignas(16) float As2[KC * PA];   // [k][2*m] duplicated rows
    __shared__ alignas(16) float Bs [KC * PB];   // [k][code]
    __shared__ float zn_s[TM];

    const int tid = threadIdx.x;
    const int tx = tid & 15, ty = tid >> 4;
    const int n0 = blockIdx.x * TM;
    const int bB  = n0 >> 12;          // batch (tile never crosses a batch: 128 | 4096)
    const int hw0 = n0 & (HW - 1);
    const float* zb = z + (size_t)bB * CHW + hw0;   // zb[c*HW + m]

    // ||z||^2 per row: mul then add (no fma), sequential over c (matches grid-level behavior)
    if (tid < TM) {
        float acc = 0.f;
        const float* p = zb + tid;
        #pragma unroll
        for (int c = 0; c < C; c++) {
            float v = p[c * HW];
            acc = __fadd_rn(acc, __fmul_rn(v, v));
        }
        zn_s[tid] = acc;
    }

    float minval[8];
    int   minidx[8];
    #pragma unroll
    for (int i = 0; i < 8; i++) { minval[i] = 3.4e38f; minidx[i] = 0; }

    for (int chunk = 0; chunk < K / TN; chunk++) {
        const int code0 = chunk * TN;

        ULL acc[8][4];
        #pragma unroll
        for (int i = 0; i < 8; i++)
            #pragma unroll
            for (int p = 0; p < 4; p++) acc[i][p] = 0ULL;

        for (int s = 0; s < C / KC; s++) {
            const int k0 = s * KC;
            __syncthreads();
            // Load A tile (rows duplicated pairwise so LDS.64 yields (a,a))
            #pragma unroll
            for (int t = 0; t < 8; t++) {
                int f = tid + 256 * t;            // 2048 elems
                int m = f & 127, k = f >> 7;
                float v = zb[(k0 + k) * HW + m];
                ((float2*)(As2 + k * PA))[m] = make_float2(v, v);
            }
            // Load B tile transposed: Bs[k][code]
            #pragma unroll
            for (int t = 0; t < 8; t++) {
                int f = tid + 256 * t;
                int k = f & (KC - 1), nn = f >> 4;
                Bs[k * PB + nn] = emb[(code0 + nn) * C + k0 + k];
            }
            __syncthreads();

            #pragma unroll
            for (int k = 0; k < KC; k++) {
                ULL a[8];
                #pragma unroll
                for (int i = 0; i < 8; i++)
                    a[i] = *(const ULL*)(As2 + k * PA + 2 * (ty * 8 + i));
                #pragma unroll
                for (int p = 0; p < 4; p++) {
                    ULL b = *(const ULL*)(Bs + k * PB + 2 * tx + 32 * p);
                    #pragma unroll
                    for (int i = 0; i < 8; i++)
                        asm("fma.rn.f32x2 %0, %1, %2, %0;"
                            : "+l"(acc[i][p]) : "l"(a[i]), "l"(b));
                }
            }
        }

        // Chunk epilogue: scores -> running min (codes visited in ascending order)
        #pragma unroll
        for (int i = 0; i < 8; i++) {
            float zn = zn_s[ty * 8 + i];
            #pragma unroll
            for (int p = 0; p < 4; p++) {
                unsigned lo32 = (unsigned)(acc[i][p] & 0xffffffffULL);
                unsigned hi32 = (unsigned)(acc[i][p] >> 32);
                float slo = __uint_as_float(lo32);
                float shi = __uint_as_float(hi32);
                int clo = code0 + 32 * p + 2 * tx;
                float dlo = __fadd_rn(__fadd_rn(zn, -2.0f * slo), g_enorm[clo]);
                float dhi = __fadd_rn(__fadd_rn(zn, -2.0f * shi), g_enorm[clo + 1]);
                if (dlo < minval[i]) { minval[i] = dlo; minidx[i] = clo; }
                if (dhi < minval[i]) { minval[i] = dhi; minidx[i] = clo + 1; }
            }
        }
    }

    // Cross-thread reduction: 16 threads (tx) share each row. Lexicographic (val, idx).
    __syncthreads();
    float* rv = As2;            // 2048 floats
    int*   ri = (int*)Bs;       // 2048 ints
    #pragma unroll
    for (int i = 0; i < 8; i++) {
        rv[tx * TM + ty * 8 + i] = minval[i];
        ri[tx * TM + ty * 8 + i] = minidx[i];
    }
    __syncthreads();
    if (tid < TM) {
        float bv = rv[tid];
        int   bi = ri[tid];
        #pragma unroll
        for (int t = 1; t < 16; t++) {
            float v  = rv[t * TM + tid];
            int   ix = ri[t * TM + tid];
            if (v < bv || (v == bv && ix < bi)) { bv = v; bi = ix; }
        }
        g_idx[n0 + tid] = bi;
    }
}

// ---------------------------------------------------------------------------
// Kernel 2: gather codes, straight-through output, partial loss sums.
// q_st = z + (q - z) with explicit fp32 rounding (matches reference's
// cancellation noise). diff^2 accumulated in double per thread.
// ---------------------------------------------------------------------------
__global__ void gather_kernel(const float* __restrict__ z,
                              const float* __restrict__ emb,
                              float* __restrict__ out) {
    int n = blockIdx.x * blockDim.x + threadIdx.x;   // 65536 threads
    int b = n >> 12, hw = n & (HW - 1);
    const float* zp = z + (size_t)b * CHW + hw;
    float* op = out + (size_t)b * CHW + hw;
    int idx = g_idx[n];
    const float* e = emb + idx * C;

    double s = 0.0;
    #pragma unroll
    for (int c = 0; c < C; c++) {
        float zv   = zp[c * HW];
        float q    = __ldg(e + c);
        float diff = __fadd_rn(q, -zv);         // (q - z), fp32 rounded
        float qst  = __fadd_rn(zv, diff);       // z + (q - z)
        op[c * HW] = qst;
        float d2 = __fmul_rn(diff, diff);
        s += (double)d2;
    }

    __shared__ double sd[256];
    sd[threadIdx.x] = s;
    __syncthreads();
    for (int st = 128; st > 0; st >>= 1) {
        if (threadIdx.x < st) sd[threadIdx.x] += sd[threadIdx.x + st];
        __syncthreads();
    }
    if (threadIdx.x == 0) g_partials[blockIdx.x] = sd[0];
}

// ---------------------------------------------------------------------------
// Kernel 3: deterministic final loss. loss = m + 0.25f*m (ref op order).
// ---------------------------------------------------------------------------
__global__ void loss_kernel(float* __restrict__ out) {
    if (threadIdx.x == 0 && blockIdx.x == 0) {
        double s = 0.0;
        for (int i = 0; i < 256; i++) s += g_partials[i];
        float m = (float)(s / (double)((size_t)N * C));
        float loss = __fadd_rn(m, 0.25f * m);
        out[(size_t)N * C] = loss;   // element 4194304
    }
}

// ---------------------------------------------------------------------------
extern "C" void kernel_launch(void* const* d_in, const int* in_sizes, int n_in,
                              void* d_out, int out_size) {
    const float* z   = (const float*)d_in[0];   // [16,64,64,64]
    const float* emb = (const float*)d_in[1];   // [1024,64]
    float* out = (float*)d_out;                 // 4194304 q_st + 1 loss

    enorm_kernel <<< (K + 255) / 256, 256 >>>(emb);
    argmin_kernel<<< N / TM,          256 >>>(z, emb);
    gather_kernel<<< N / 256,         256 >>>(z, emb, out);
    loss_kernel  <<< 1,               32  >>>(out);
}

// round 2
// speedup vs baseline: 1.2578x; 1.2578x over previous
#include <cuda_runtime.h>
#include <cstdint>

typedef unsigned long long ULL;

// Problem constants (fixed shapes per reference)
constexpr int Bz = 16, C = 64, H = 64, W = 64;
constexpr int N  = Bz * H * W;     // 65536 rows
constexpr int K  = 1024;           // codes
constexpr int HW = H * W;          // 4096
constexpr int CHW = C * HW;        // 262144

// argmin tiling: tile = 64 rows x all 1024 codes (8 chunks of 128)
// threads 256 = tx16 (codes, n=8 each) x ty16 (rows, m=4 each)
constexpr int TM = 64;
constexpr int TN = 128;
constexpr int P  = 66;             // smem pitch in floats (bank-conflict-free)
constexpr int NTILES = N / TM;     // 1024
constexpr int NCHUNK = K / TN;     // 8

// dynamic smem layout (floats)
constexpr int SM_AS  = 0;                       // As[64][66]
constexpr int SM_BS  = TM * P;                  // 4224: Bs[2][128][66]
constexpr int SM_BSZ = TN * P;                  // 8448 per buffer
constexpr int SM_RED = SM_BS + 2 * SM_BSZ;      // 21120: ULL red[16][64] (2048 fl)
constexpr int SM_ZN  = SM_RED + 2048;           // 23168: zn[64]
constexpr int SM_TOT = SM_ZN + TM;              // 23232 floats = 92928 bytes
constexpr int SMEM_BYTES = SM_TOT * 4;

// Device scratch (no allocations allowed)
__device__ int    g_idx[N];
__device__ float  g_enorm[K];
__device__ double g_partials[256];
__device__ int    g_ticket;

__device__ __forceinline__ void cp_async8(uint32_t dst_smem, const float* src) {
    asm volatile("cp.async.ca.shared.global [%0], [%1], 8;\n"
                 :: "r"(dst_smem), "l"(src));
}

// ---------------------------------------------------------------------------
// Kernel 0: ||e_k||^2 per code (reference rounding: mul then sequential adds).
// Also resets the work-stealing ticket for the argmin kernel.
// ---------------------------------------------------------------------------
__global__ void enorm_kernel(const float* __restrict__ emb) {
    if (blockIdx.x == 0 && threadIdx.x == 0) g_ticket = 0;
    int code = blockIdx.x * blockDim.x + threadIdx.x;
    if (code < K) {
        const float* e = emb + code * C;
        float acc = 0.f;
        #pragma unroll
        for (int c = 0; c < C; c++) {
            float v = e[c];
            acc = __fadd_rn(acc, __fmul_rn(v, v));
        }
        g_enorm[code] = acc;
    }
}

// ---------------------------------------------------------------------------
// Kernel 1: fused fp32 score + per-row argmin, k-pair FFMA2 vectorization.
// Persistent blocks pull 64-row tiles via atomic ticket.
// acc[i][j] is a packed pair: (sum over even k, sum over odd k); combined
// with one fp32 add. d = (zn - 2S) + en on the reference's fp32 grid.
// ---------------------------------------------------------------------------
__global__ __launch_bounds__(256, 2)
void argmin_kernel(const float* __restrict__ z, const float* __restrict__ emb) {
    extern __shared__ float sm[];
    float* As   = sm + SM_AS;
    float* Bs   = sm + SM_BS;
    ULL*   red  = (ULL*)(sm + SM_RED);
    float* zn_s = sm + SM_ZN;
    __shared__ int s_tile;

    const uint32_t sbase = (uint32_t)__cvta_generic_to_shared(sm);
    const int tid = threadIdx.x;
    const int tx = tid & 15, ty = tid >> 4;

    for (;;) {
        if (tid == 0) s_tile = atomicAdd(&g_ticket, 1);
        __syncthreads();
        const int tile = s_tile;
        if (tile >= NTILES) return;

        const int n0 = tile * TM;
        const int bB  = n0 >> 12;             // 64 | 4096: tile never crosses batch
        const int hw0 = n0 & (HW - 1);
        const float* zb = z + (size_t)bB * CHW + hw0;   // zb[k*HW + m]

        // Load A tile [64 rows][64 k], k-minor, coalesced global reads.
        #pragma unroll
        for (int t = 0; t < 16; t++) {
            int f = tid + 256 * t;            // 4096 elems
            int m = f & 63, k = f >> 6;
            As[m * P + k] = zb[k * HW + m];
        }
        // ||z||^2 per row (reference op order).
        if (tid < TM) {
            float acc = 0.f;
            const float* p = zb + tid;
            #pragma unroll
            for (int c = 0; c < C; c++) {
                float v = p[c * HW];
                acc = __fadd_rn(acc, __fmul_rn(v, v));
            }
            zn_s[tid] = acc;
        }
        // Prefetch B chunk 0 (codes 0..127, k-minor) via cp.async.
        #pragma unroll
        for (int t = 0; t < 16; t++) {
            int q = tid + 256 * t;            // 4096 8-byte chunks
            int code = q >> 5, kp = q & 31;
            uint32_t dst = sbase + (uint32_t)((SM_BS + code * P + 2 * kp) * 4);
            cp_async8(dst, emb + code * 64 + 2 * kp);
        }
        asm volatile("cp.async.commit_group;\n");

        float minval[4];
        int   minidx[4];
        #pragma unroll
        for (int i = 0; i < 4; i++) { minval[i] = 3.4e38f; minidx[i] = 0; }

        for (int chunk = 0; chunk < NCHUNK; chunk++) {
            // Prefetch next chunk's B into the other buffer.
            if (chunk + 1 < NCHUNK) {
                const int code0n = (chunk + 1) * TN;
                const int bufn = (chunk + 1) & 1;
                #pragma unroll
                for (int t = 0; t < 16; t++) {
                    int q = tid + 256 * t;
                    int code = q >> 5, kp = q & 31;
                    uint32_t dst = sbase +
                        (uint32_t)((SM_BS + bufn * SM_BSZ + code * P + 2 * kp) * 4);
                    cp_async8(dst, emb + (code0n + code) * 64 + 2 * kp);
                }
                asm volatile("cp.async.commit_group;\n");
                asm volatile("cp.async.wait_group 1;\n");
            } else {
                asm volatile("cp.async.wait_group 0;\n");
            }
            __syncthreads();

            const float* Ab = As + (ty * 4) * P;
            const float* Bb = Bs + (chunk & 1) * SM_BSZ + tx * P;

            ULL acc[4][8];
            #pragma unroll
            for (int i = 0; i < 4; i++)
                #pragma unroll
                for (int j = 0; j < 8; j++) acc[i][j] = 0ULL;

            #pragma unroll 8
            for (int kk = 0; kk < 32; kk++) {     // kk = k-pair index
                ULL a[4], b[8];
                #pragma unroll
                for (int i = 0; i < 4; i++)
                    a[i] = *(const ULL*)(Ab + i * P + 2 * kk);
                #pragma unroll
                for (int j = 0; j < 8; j++)
                    b[j] = *(const ULL*)(Bb + j * 16 * P + 2 * kk);
                #pragma unroll
                for (int j = 0; j < 8; j++)
                    #pragma unroll
                    for (int i = 0; i < 4; i++)
                        asm("fma.rn.f32x2 %0, %1, %2, %0;"
                            : "+l"(acc[i][j]) : "l"(a[i]), "l"(b[j]));
            }

            // Chunk epilogue: combine pair halves, score, running min.
            const int code0 = chunk * TN;
            #pragma unroll
            for (int i = 0; i < 4; i++) {
                float zn = zn_s[ty * 4 + i];
                #pragma unroll
                for (int j = 0; j < 8; j++) {
                    float slo = __uint_as_float((unsigned)(acc[i][j] & 0xffffffffULL));
                    float shi = __uint_as_float((unsigned)(acc[i][j] >> 32));
                    float S   = __fadd_rn(slo, shi);
                    int code  = code0 + tx + 16 * j;
                    float d = __fadd_rn(__fadd_rn(zn, -2.0f * S), g_enorm[code]);
                    if (d < minval[i]) { minval[i] = d; minidx[i] = code; }
                }
            }
            __syncthreads();   // protect B buffer reuse (chunk+1 writes buf[chunk&1])
        }

        // Cross-thread reduce: 16 tx threads share each row.
        // Pack (valbits, idx) so min = lexicographic (val, then lowest index).
        // d >= 0 always here, so float bits are order-preserving.
        #pragma unroll
        for (int i = 0; i < 4; i++) {
            ULL key = ((ULL)__float_as_uint(minval[i]) << 32) | (unsigned)minidx[i];
            red[tx * TM + ty * 4 + i] = key;
        }
        __syncthreads();
        if (tid < TM) {
            ULL best = red[tid];
            #pragma unroll
            for (int t = 1; t < 16; t++) {
                ULL v = red[t * TM + tid];
                if (v < best) best = v;
            }
            g_idx[n0 + tid] = (int)(best & 0xffffffffULL);
        }
        __syncthreads();   // before next tile overwrites s_tile / smem
    }
}

// ---------------------------------------------------------------------------
// Kernel 2: gather codes, straight-through output, partial loss sums.
// q_st = z + (q - z) with explicit fp32 rounding (matches reference).
// ---------------------------------------------------------------------------
__global__ void gather_kernel(const float* __restrict__ z,
                              const float* __restrict__ emb,
                              float* __restrict__ out) {
    int n = blockIdx.x * blockDim.x + threadIdx.x;   // 65536 threads
    int b = n >> 12, hw = n & (HW - 1);
    const float* zp = z + (size_t)b * CHW + hw;
    float* op = out + (size_t)b * CHW + hw;
    int idx = g_idx[n];
    const float* e = emb + idx * C;

    double s = 0.0;
    #pragma unroll
    for (int c = 0; c < C; c++) {
        float zv   = zp[c * HW];
        float q    = __ldg(e + c);
        float diff = __fadd_rn(q, -zv);
        float qst  = __fadd_rn(zv, diff);
        op[c * HW] = qst;
        s += (double)__fmul_rn(diff, diff);
    }

    __shared__ double sd[256];
    sd[threadIdx.x] = s;
    __syncthreads();
    for (int st = 128; st > 0; st >>= 1) {
        if (threadIdx.x < st) sd[threadIdx.x] += sd[threadIdx.x + st];
        __syncthreads();
    }
    if (threadIdx.x == 0) g_partials[blockIdx.x] = sd[0];
}

// ---------------------------------------------------------------------------
// Kernel 3: parallel deterministic final loss. loss = m + 0.25f*m.
// ---------------------------------------------------------------------------
__global__ void loss_kernel(float* __restrict__ out) {
    __shared__ double sd[256];
    int t = threadIdx.x;
    sd[t] = g_partials[t];
    __syncthreads();
    for (int st = 128; st > 0; st >>= 1) {
        if (t < st) sd[t] += sd[t + st];
        __syncthreads();
    }
    if (t == 0) {
        float m = (float)(sd[0] / (double)((size_t)N * C));
        out[(size_t)N * C] = __fadd_rn(m, 0.25f * m);
    }
}

// ---------------------------------------------------------------------------
extern "C" void kernel_launch(void* const* d_in, const int* in_sizes, int n_in,
                              void* d_out, int out_size) {
    const float* z   = (const float*)d_in[0];   // [16,64,64,64]
    const float* emb = (const float*)d_in[1];   // [1024,64]
    float* out = (float*)d_out;                 // 4194304 q_st + 1 loss

    cudaFuncSetAttribute(argmin_kernel,
                         cudaFuncAttributeMaxDynamicSharedMemorySize, SMEM_BYTES);

    enorm_kernel <<< (K + 255) / 256, 256 >>>(emb);
    argmin_kernel<<< 296, 256, SMEM_BYTES >>>(z, emb);
    gather_kernel<<< N / 256, 256 >>>(z, emb, out);
    loss_kernel  <<< 1, 256 >>>(out);
}